// round 1
// baseline (speedup 1.0000x reference)
#include <cuda_runtime.h>
#include <math.h>

#define N_NODES 50000
#define N_EDGES 800000
#define IN_DIM 50
#define HID 64
#define HEADS 4
#define CH 16
#define NLAYERS 3
#define NC 12
#define INV_SQRT_C 0.25f
#define LN_EPS 1e-5f

// ---------------- scratch (device globals; no allocation allowed) -------------
__device__ float g_h[N_NODES * HID];
__device__ float g_q[N_NODES * HID];
__device__ float g_k[N_NODES * HID];
__device__ float g_v[N_NODES * HID];
__device__ float g_skip[N_NODES * HID];
__device__ int   g_cnt[N_NODES];
__device__ int   g_rowptr[N_NODES + 1];
__device__ int   g_fill[N_NODES];
__device__ int   g_srcs[N_EDGES];
__device__ float g_eas[N_EDGES];

// ---------------- CSR build --------------------------------------------------
__global__ void k_zero_cnt() {
    int i = blockIdx.x * blockDim.x + threadIdx.x;
    if (i < N_NODES) g_cnt[i] = 0;
}

__global__ void k_hist(const int* __restrict__ ei) {
    int e = blockIdx.x * blockDim.x + threadIdx.x;
    if (e < N_EDGES) atomicAdd(&g_cnt[ei[N_EDGES + e]], 1);
}

// single-block exclusive scan of g_cnt -> g_rowptr / g_fill
__global__ void k_scan() {
    __shared__ int wsum[32];
    __shared__ int carry;
    int t = threadIdx.x, lane = t & 31, wid = t >> 5;
    if (t == 0) carry = 0;
    __syncthreads();
    for (int base = 0; base < N_NODES; base += 1024) {
        int i = base + t;
        int v = (i < N_NODES) ? g_cnt[i] : 0;
        int incl = v;
        #pragma unroll
        for (int o = 1; o < 32; o <<= 1) {
            int u = __shfl_up_sync(0xffffffffu, incl, o);
            if (lane >= o) incl += u;
        }
        if (lane == 31) wsum[wid] = incl;
        __syncthreads();
        if (wid == 0) {
            int ws = wsum[lane];
            int wincl = ws;
            #pragma unroll
            for (int o = 1; o < 32; o <<= 1) {
                int u = __shfl_up_sync(0xffffffffu, wincl, o);
                if (lane >= o) wincl += u;
            }
            wsum[lane] = wincl - ws;   // exclusive warp offset
        }
        __syncthreads();
        int excl = incl - v + wsum[wid] + carry;
        if (i < N_NODES) { g_rowptr[i] = excl; g_fill[i] = excl; }
        __syncthreads();
        if (t == 1023) carry = excl + v;
        __syncthreads();
    }
    if (t == 0) g_rowptr[N_NODES] = carry;
}

__global__ void k_scatter(const int* __restrict__ ei, const float* __restrict__ ea) {
    int e = blockIdx.x * blockDim.x + threadIdx.x;
    if (e < N_EDGES) {
        int dst = ei[N_EDGES + e];
        int pos = atomicAdd(&g_fill[dst], 1);
        g_srcs[pos] = ei[e];
        g_eas[pos]  = ea[e];
    }
}

// ---------------- input GEMM: h = x @ Win + b_in ------------------------------
// block = 64 threads (one output col each, weight column in regs), 64 rows/block
__global__ void k_ingemm(const float* __restrict__ x,
                         const float* __restrict__ Win,
                         const float* __restrict__ b_in) {
    __shared__ __align__(16) float xs[64 * 52];
    int c = threadIdx.x;
    float wr[52];
    #pragma unroll
    for (int k = 0; k < IN_DIM; k++) wr[k] = Win[k * HID + c];
    wr[50] = 0.f; wr[51] = 0.f;
    int n0 = blockIdx.x * 64;
    for (int idx = c; idx < 64 * IN_DIM; idx += 64) {
        int r = idx / IN_DIM, k = idx % IN_DIM;
        int row = n0 + r;
        xs[r * 52 + k] = (row < N_NODES) ? x[row * IN_DIM + k] : 0.f;
    }
    xs[c * 52 + 50] = 0.f;
    xs[c * 52 + 51] = 0.f;
    __syncthreads();
    float bias = b_in[c];
    int rmax = min(64, N_NODES - n0);
    for (int r = 0; r < rmax; r++) {
        const float4* hr = (const float4*)&xs[r * 52];
        float acc = bias;
        #pragma unroll
        for (int kk = 0; kk < 13; kk++) {
            float4 hv = hr[kk];
            acc = fmaf(wr[4 * kk + 0], hv.x, acc);
            acc = fmaf(wr[4 * kk + 1], hv.y, acc);
            acc = fmaf(wr[4 * kk + 2], hv.z, acc);
            acc = fmaf(wr[4 * kk + 3], hv.w, acc);
        }
        g_h[(n0 + r) * HID + c] = acc;
    }
}

// ---------------- per-layer fused q/k/v/skip GEMM -----------------------------
// block = 256 threads: mat = t/64 (q,k,v,skip), col = t%64. 64 rows per block.
__global__ void k_gemm4(int li,
                        const float* __restrict__ Wq, const float* __restrict__ bq,
                        const float* __restrict__ Wk, const float* __restrict__ bk,
                        const float* __restrict__ Wv, const float* __restrict__ bv,
                        const float* __restrict__ Wsk, const float* __restrict__ bsk) {
    __shared__ __align__(16) float hs[64 * 64];
    int t = threadIdx.x;
    int mat = t >> 6, c = t & 63;
    const float* W; const float* b; float* out;
    if (mat == 0)      { W = Wq  + li * 4096; b = bq  + li * 64; out = g_q; }
    else if (mat == 1) { W = Wk  + li * 4096; b = bk  + li * 64; out = g_k; }
    else if (mat == 2) { W = Wv  + li * 4096; b = bv  + li * 64; out = g_v; }
    else               { W = Wsk + li * 4096; b = bsk + li * 64; out = g_skip; }
    float wr[64];
    #pragma unroll
    for (int k = 0; k < 64; k++) wr[k] = W[k * 64 + c];
    float bias = b[c];
    float scal = (mat == 0) ? INV_SQRT_C : 1.f;
    int n0 = blockIdx.x * 64;
    float4* hs4 = (float4*)hs;
    for (int idx = t; idx < 1024; idx += 256) {
        int row = n0 + (idx >> 4);
        hs4[idx] = (row < N_NODES) ? ((const float4*)g_h)[row * 16 + (idx & 15)]
                                   : make_float4(0.f, 0.f, 0.f, 0.f);
    }
    __syncthreads();
    int rmax = min(64, N_NODES - n0);
    for (int r = 0; r < rmax; r++) {
        const float4* hr = (const float4*)&hs[r * 64];
        float acc = bias;
        #pragma unroll
        for (int kk = 0; kk < 16; kk++) {
            float4 hv = hr[kk];
            acc = fmaf(wr[4 * kk + 0], hv.x, acc);
            acc = fmaf(wr[4 * kk + 1], hv.y, acc);
            acc = fmaf(wr[4 * kk + 2], hv.z, acc);
            acc = fmaf(wr[4 * kk + 3], hv.w, acc);
        }
        out[(n0 + r) * 64 + c] = acc * scal;
    }
}

// ---------------- fused node kernel: online softmax + gate + residual + LN ----
// one 64-thread block per node; thread t owns feature t, head = t/16
__global__ void k_node(int li,
                       const float* __restrict__ Wedge,
                       const float* __restrict__ Wbeta,
                       const float* __restrict__ lng,
                       const float* __restrict__ lnb) {
    int n = blockIdx.x;
    int t = threadIdx.x, lane = t & 31, wid = t >> 5;
    __shared__ float red[2];

    float qt = g_q[n * 64 + t];             // already scaled by 1/sqrt(C)
    float we = Wedge[li * 64 + t];

    float m = -INFINITY, d = 0.f, acc = 0.f;
    int s0 = g_rowptr[n], s1 = g_rowptr[n + 1];
    for (int j = s0; j < s1; j++) {
        int   s = g_srcs[j];
        float w = g_eas[j];
        float ew = w * we;
        float ke = g_k[s * 64 + t] + ew;
        float p = qt * ke;
        p += __shfl_xor_sync(0xffffffffu, p, 8, 16);
        p += __shfl_xor_sync(0xffffffffu, p, 4, 16);
        p += __shfl_xor_sync(0xffffffffu, p, 2, 16);
        p += __shfl_xor_sync(0xffffffffu, p, 1, 16);
        float a  = p;                        // per-head logit, replicated in 16 lanes
        float mn = fmaxf(m, a);
        float sc = __expf(m - mn);
        float ex = __expf(a - mn);
        float ve = g_v[s * 64 + t] + ew;
        d   = d * sc + ex;
        acc = acc * sc + ve * ex;
        m = mn;
    }
    float outv = acc / (d + 1e-16f);

    float xr = g_skip[n * 64 + t];
    // beta = sigmoid([out, xr, out-xr] @ Wbeta)
    float contrib = outv * Wbeta[li * 192 + t]
                  + xr   * Wbeta[li * 192 + 64 + t]
                  + (outv - xr) * Wbeta[li * 192 + 128 + t];
    float s = contrib;
    #pragma unroll
    for (int o = 16; o >= 1; o >>= 1) s += __shfl_xor_sync(0xffffffffu, s, o);
    if (lane == 0) red[wid] = s;
    __syncthreads();
    float tot = red[0] + red[1];
    __syncthreads();
    float beta = 1.f / (1.f + __expf(-tot));
    float og = beta * xr + (1.f - beta) * outv;
    float z = og + g_h[n * 64 + t];

    // layernorm over 64
    s = z;
    #pragma unroll
    for (int o = 16; o >= 1; o >>= 1) s += __shfl_xor_sync(0xffffffffu, s, o);
    if (lane == 0) red[wid] = s;
    __syncthreads();
    float mu = (red[0] + red[1]) * (1.f / 64.f);
    __syncthreads();
    float dz = z - mu;
    s = dz * dz;
    #pragma unroll
    for (int o = 16; o >= 1; o >>= 1) s += __shfl_xor_sync(0xffffffffu, s, o);
    if (lane == 0) red[wid] = s;
    __syncthreads();
    float var = (red[0] + red[1]) * (1.f / 64.f);
    float hn = dz * rsqrtf(var + LN_EPS) * lng[li * 64 + t] + lnb[li * 64 + t];
    g_h[n * 64 + t] = hn;
}

// ---------------- head: out = relu(h@Wc1+bc1)@Wc2+bc2 -------------------------
// block = 128 threads, 64 rows per block
__global__ void k_final(const float* __restrict__ Wc1, const float* __restrict__ bc1,
                        const float* __restrict__ Wc2, const float* __restrict__ bc2,
                        float* __restrict__ out) {
    __shared__ __align__(16) float hs[64 * 64];
    __shared__ __align__(16) float h1s[64 * 64];
    int t = threadIdx.x;
    int n0 = blockIdx.x * 64;
    float4* hs4 = (float4*)hs;
    for (int idx = t; idx < 1024; idx += 128) {
        int row = n0 + (idx >> 4);
        hs4[idx] = (row < N_NODES) ? ((const float4*)g_h)[row * 16 + (idx & 15)]
                                   : make_float4(0.f, 0.f, 0.f, 0.f);
    }
    int c = t & 63, rg = t >> 6;       // 2 row-groups of 32
    float wr[64];
    #pragma unroll
    for (int k = 0; k < 64; k++) wr[k] = Wc1[k * 64 + c];
    float b1 = bc1[c];
    __syncthreads();
    for (int r = rg * 32; r < rg * 32 + 32; r++) {
        const float4* hr = (const float4*)&hs[r * 64];
        float acc = b1;
        #pragma unroll
        for (int kk = 0; kk < 16; kk++) {
            float4 hv = hr[kk];
            acc = fmaf(wr[4 * kk + 0], hv.x, acc);
            acc = fmaf(wr[4 * kk + 1], hv.y, acc);
            acc = fmaf(wr[4 * kk + 2], hv.z, acc);
            acc = fmaf(wr[4 * kk + 3], hv.w, acc);
        }
        h1s[r * 64 + c] = fmaxf(acc, 0.f);
    }
    __syncthreads();
    if (t < 120) {
        int c2 = t % 12, rg2 = t / 12;  // 10 row-groups
        float wr2[64];
        #pragma unroll
        for (int k = 0; k < 64; k++) wr2[k] = Wc2[k * NC + c2];
        float b2 = bc2[c2];
        int rmax = min(64, N_NODES - n0);
        for (int r = rg2; r < rmax; r += 10) {
            const float4* hr = (const float4*)&h1s[r * 64];
            float acc = b2;
            #pragma unroll
            for (int kk = 0; kk < 16; kk++) {
                float4 hv = hr[kk];
                acc = fmaf(wr2[4 * kk + 0], hv.x, acc);
                acc = fmaf(wr2[4 * kk + 1], hv.y, acc);
                acc = fmaf(wr2[4 * kk + 2], hv.z, acc);
                acc = fmaf(wr2[4 * kk + 3], hv.w, acc);
            }
            out[(n0 + r) * NC + c2] = acc;
        }
    }
}

// ---------------- launch -----------------------------------------------------
extern "C" void kernel_launch(void* const* d_in, const int* in_sizes, int n_in,
                              void* d_out, int out_size) {
    const float* x     = (const float*)d_in[0];
    const int*   ei    = (const int*)  d_in[1];
    const float* ea    = (const float*)d_in[2];
    const float* Win   = (const float*)d_in[3];
    const float* b_in  = (const float*)d_in[4];
    const float* Wq    = (const float*)d_in[5];
    const float* bq    = (const float*)d_in[6];
    const float* Wk    = (const float*)d_in[7];
    const float* bk    = (const float*)d_in[8];
    const float* Wv    = (const float*)d_in[9];
    const float* bv    = (const float*)d_in[10];
    const float* Wedge = (const float*)d_in[11];
    const float* Wskip = (const float*)d_in[12];
    const float* bskip = (const float*)d_in[13];
    const float* Wbeta = (const float*)d_in[14];
    const float* ln_g  = (const float*)d_in[15];
    const float* ln_b  = (const float*)d_in[16];
    const float* Wc1   = (const float*)d_in[17];
    const float* bc1   = (const float*)d_in[18];
    const float* Wc2   = (const float*)d_in[19];
    const float* bc2   = (const float*)d_in[20];
    float* out = (float*)d_out;

    int nrb = (N_NODES + 63) / 64;   // 64-row GEMM tiles

    k_zero_cnt<<<(N_NODES + 255) / 256, 256>>>();
    k_hist<<<(N_EDGES + 255) / 256, 256>>>(ei);
    k_scan<<<1, 1024>>>();
    k_scatter<<<(N_EDGES + 255) / 256, 256>>>(ei, ea);

    k_ingemm<<<nrb, 64>>>(x, Win, b_in);

    for (int li = 0; li < NLAYERS; li++) {
        k_gemm4<<<nrb, 256>>>(li, Wq, bq, Wk, bk, Wv, bv, Wskip, bskip);
        k_node<<<N_NODES, 64>>>(li, Wedge, Wbeta, ln_g, ln_b);
    }

    k_final<<<nrb, 128>>>(Wc1, bc1, Wc2, bc2, out);
}

// round 2
// speedup vs baseline: 1.2030x; 1.2030x over previous
#include <cuda_runtime.h>
#include <math.h>

#define N_NODES 50000
#define N_EDGES 800000
#define IN_DIM 50
#define HID 64
#define HEADS 4
#define CH 16
#define NLAYERS 3
#define NC 12
#define INV_SQRT_C 0.25f
#define LN_EPS 1e-5f
#define SCAN_BLK ((N_NODES + 1023) / 1024)   // 49

// ---------------- scratch (device globals; no allocation allowed) -------------
__device__ float g_h[N_NODES * HID];
__device__ float g_q[N_NODES * HID];
__device__ float g_k[N_NODES * HID];
__device__ float g_v[N_NODES * HID];
__device__ float g_skip[N_NODES * HID];
__device__ int   g_cnt[N_NODES];
__device__ int   g_rowptr[N_NODES + 1];
__device__ int   g_fill[N_NODES];
__device__ int   g_srcs[N_EDGES];
__device__ float g_eas[N_EDGES];
__device__ int   g_psum[64];

// ---------------- CSR build --------------------------------------------------
__global__ void k_zero_cnt() {
    int i = blockIdx.x * blockDim.x + threadIdx.x;
    if (i < N_NODES) g_cnt[i] = 0;
}

__global__ void k_hist(const int* __restrict__ ei) {
    int e = blockIdx.x * blockDim.x + threadIdx.x;
    if (e < N_EDGES) atomicAdd(&g_cnt[ei[N_EDGES + e]], 1);
}

// per-block local exclusive scan + block sums
__global__ void k_scan1() {
    __shared__ int wsum[32];
    int t = threadIdx.x, lane = t & 31, wid = t >> 5;
    int i = blockIdx.x * 1024 + t;
    int v = (i < N_NODES) ? g_cnt[i] : 0;
    int incl = v;
    #pragma unroll
    for (int o = 1; o < 32; o <<= 1) {
        int u = __shfl_up_sync(0xffffffffu, incl, o);
        if (lane >= o) incl += u;
    }
    if (lane == 31) wsum[wid] = incl;
    __syncthreads();
    if (wid == 0) {
        int ws = wsum[lane];
        int wincl = ws;
        #pragma unroll
        for (int o = 1; o < 32; o <<= 1) {
            int u = __shfl_up_sync(0xffffffffu, wincl, o);
            if (lane >= o) wincl += u;
        }
        wsum[lane] = wincl - ws;
        if (lane == 31) g_psum[blockIdx.x] = wincl;
    }
    __syncthreads();
    int excl = incl - v + wsum[wid];
    if (i < N_NODES) g_rowptr[i] = excl;
}

// scan the 49 block sums (single block, 64 threads)
__global__ void k_scan2() {
    __shared__ int w0tot;
    int t = threadIdx.x, lane = t & 31;
    int v = (t < SCAN_BLK) ? g_psum[t] : 0;
    int incl = v;
    #pragma unroll
    for (int o = 1; o < 32; o <<= 1) {
        int u = __shfl_up_sync(0xffffffffu, incl, o);
        if (lane >= o) incl += u;
    }
    if (t == 31) w0tot = incl;
    __syncthreads();
    int excl = incl - v + ((t >= 32) ? w0tot : 0);
    if (t < SCAN_BLK) g_psum[t] = excl;
}

// add block offsets, produce rowptr + fill
__global__ void k_scan3() {
    int i = blockIdx.x * blockDim.x + threadIdx.x;
    if (i < N_NODES) {
        int r = g_rowptr[i] + g_psum[i >> 10];
        g_rowptr[i] = r;
        g_fill[i] = r;
    }
    if (i == 0) g_rowptr[N_NODES] = N_EDGES;
}

__global__ void k_scatter(const int* __restrict__ ei, const float* __restrict__ ea) {
    int e = blockIdx.x * blockDim.x + threadIdx.x;
    if (e < N_EDGES) {
        int dst = ei[N_EDGES + e];
        int pos = atomicAdd(&g_fill[dst], 1);
        g_srcs[pos] = ei[e];
        g_eas[pos]  = ea[e];
    }
}

// ---------------- input GEMM: h = x @ Win + b_in ------------------------------
__global__ void k_ingemm(const float* __restrict__ x,
                         const float* __restrict__ Win,
                         const float* __restrict__ b_in) {
    __shared__ __align__(16) float xs[64 * 52];
    int c = threadIdx.x;
    float wr[52];
    #pragma unroll
    for (int k = 0; k < IN_DIM; k++) wr[k] = Win[k * HID + c];
    wr[50] = 0.f; wr[51] = 0.f;
    int n0 = blockIdx.x * 64;
    for (int idx = c; idx < 64 * IN_DIM; idx += 64) {
        int r = idx / IN_DIM, k = idx % IN_DIM;
        int row = n0 + r;
        xs[r * 52 + k] = (row < N_NODES) ? x[row * IN_DIM + k] : 0.f;
    }
    xs[c * 52 + 50] = 0.f;
    xs[c * 52 + 51] = 0.f;
    __syncthreads();
    float bias = b_in[c];
    int rmax = min(64, N_NODES - n0);
    for (int r = 0; r < rmax; r++) {
        const float4* hr = (const float4*)&xs[r * 52];
        float acc = bias;
        #pragma unroll
        for (int kk = 0; kk < 13; kk++) {
            float4 hv = hr[kk];
            acc = fmaf(wr[4 * kk + 0], hv.x, acc);
            acc = fmaf(wr[4 * kk + 1], hv.y, acc);
            acc = fmaf(wr[4 * kk + 2], hv.z, acc);
            acc = fmaf(wr[4 * kk + 3], hv.w, acc);
        }
        g_h[(n0 + r) * HID + c] = acc;
    }
}

// ---------------- per-layer fused q/k/v/skip GEMM -----------------------------
__global__ void k_gemm4(int li,
                        const float* __restrict__ Wq, const float* __restrict__ bq,
                        const float* __restrict__ Wk, const float* __restrict__ bk,
                        const float* __restrict__ Wv, const float* __restrict__ bv,
                        const float* __restrict__ Wsk, const float* __restrict__ bsk) {
    __shared__ __align__(16) float hs[64 * 64];
    int t = threadIdx.x;
    int mat = t >> 6, c = t & 63;
    const float* W; const float* b; float* out;
    if (mat == 0)      { W = Wq  + li * 4096; b = bq  + li * 64; out = g_q; }
    else if (mat == 1) { W = Wk  + li * 4096; b = bk  + li * 64; out = g_k; }
    else if (mat == 2) { W = Wv  + li * 4096; b = bv  + li * 64; out = g_v; }
    else               { W = Wsk + li * 4096; b = bsk + li * 64; out = g_skip; }
    float scal = (mat == 0) ? INV_SQRT_C : 1.f;   // fold q-scale into weights
    float wr[64];
    #pragma unroll
    for (int k = 0; k < 64; k++) wr[k] = W[k * 64 + c] * scal;
    float bias = b[c] * scal;
    int n0 = blockIdx.x * 64;
    float4* hs4 = (float4*)hs;
    for (int idx = t; idx < 1024; idx += 256) {
        int row = n0 + (idx >> 4);
        hs4[idx] = (row < N_NODES) ? ((const float4*)g_h)[row * 16 + (idx & 15)]
                                   : make_float4(0.f, 0.f, 0.f, 0.f);
    }
    __syncthreads();
    int rmax = min(64, N_NODES - n0);
    for (int r = 0; r < rmax; r++) {
        const float4* hr = (const float4*)&hs[r * 64];
        float acc = bias;
        #pragma unroll
        for (int kk = 0; kk < 16; kk++) {
            float4 hv = hr[kk];
            acc = fmaf(wr[4 * kk + 0], hv.x, acc);
            acc = fmaf(wr[4 * kk + 1], hv.y, acc);
            acc = fmaf(wr[4 * kk + 2], hv.z, acc);
            acc = fmaf(wr[4 * kk + 3], hv.w, acc);
        }
        out[(n0 + r) * 64 + c] = acc;
    }
}

// ---------------- fused node kernel v2: warp per node ------------------------
// lane owns channels {2*lane, 2*lane+1}; head = lane>>3 (8 lanes per head)
__global__ void k_node2(int li,
                        const float* __restrict__ Wedge,
                        const float* __restrict__ Wbeta,
                        const float* __restrict__ lng,
                        const float* __restrict__ lnb) {
    int n = blockIdx.x * (blockDim.x >> 5) + (threadIdx.x >> 5);
    if (n >= N_NODES) return;
    int lane = threadIdx.x & 31;

    float2 q  = ((const float2*)g_q)[n * 32 + lane];          // pre-scaled by 1/sqrt(C)
    float2 we = ((const float2*)Wedge)[li * 32 + lane];

    // per-head dot(q, we): reduce over 8 lanes
    float pw = q.x * we.x + q.y * we.y;
    pw += __shfl_xor_sync(0xffffffffu, pw, 4, 8);
    pw += __shfl_xor_sync(0xffffffffu, pw, 2, 8);
    pw += __shfl_xor_sync(0xffffffffu, pw, 1, 8);
    float qwe = pw;

    float d = 0.f, spw = 0.f;
    float ax = 0.f, ay = 0.f;
    int j0 = g_rowptr[n], j1 = g_rowptr[n + 1];
    for (int j = j0; j < j1; j++) {
        int   s = __ldg(&g_srcs[j]);
        float w = __ldg(&g_eas[j]);
        float2 kf = ((const float2*)g_k)[s * 32 + lane];
        float p = q.x * kf.x + q.y * kf.y;
        p += __shfl_xor_sync(0xffffffffu, p, 4, 8);
        p += __shfl_xor_sync(0xffffffffu, p, 2, 8);
        p += __shfl_xor_sync(0xffffffffu, p, 1, 8);
        float a  = fmaf(w, qwe, p);
        float ex = __expf(a);                 // softmax is shift-invariant; logits O(1)
        float2 vf = ((const float2*)g_v)[s * 32 + lane];
        d   += ex;
        ax   = fmaf(ex, vf.x, ax);
        ay   = fmaf(ex, vf.y, ay);
        spw  = fmaf(ex, w, spw);
    }
    float inv = 1.f / (d + 1e-16f);
    float ox = (ax + we.x * spw) * inv;
    float oy = (ay + we.y * spw) * inv;

    // gate: beta = sigmoid([out, xr, out-xr] @ Wbeta)
    float2 xr = ((const float2*)g_skip)[n * 32 + lane];
    const float2* Wb = (const float2*)(Wbeta + li * 192);
    float2 w1 = Wb[lane], w2 = Wb[32 + lane], w3 = Wb[64 + lane];
    float contrib = ox * w1.x + oy * w1.y + xr.x * w2.x + xr.y * w2.y
                  + (ox - xr.x) * w3.x + (oy - xr.y) * w3.y;
    #pragma unroll
    for (int o = 16; o >= 1; o >>= 1)
        contrib += __shfl_xor_sync(0xffffffffu, contrib, o);
    float beta = 1.f / (1.f + __expf(-contrib));

    float2 hres = ((const float2*)g_h)[n * 32 + lane];
    float zx = fmaf(beta, xr.x - ox, ox) + hres.x;
    float zy = fmaf(beta, xr.y - oy, oy) + hres.y;

    // layernorm over 64: one pass (sum, sumsq)
    float s1 = zx + zy;
    float s2 = zx * zx + zy * zy;
    #pragma unroll
    for (int o = 16; o >= 1; o >>= 1) {
        s1 += __shfl_xor_sync(0xffffffffu, s1, o);
        s2 += __shfl_xor_sync(0xffffffffu, s2, o);
    }
    float mu  = s1 * (1.f / 64.f);
    float var = s2 * (1.f / 64.f) - mu * mu;
    float rstd = rsqrtf(var + LN_EPS);
    float2 g = ((const float2*)lng)[li * 32 + lane];
    float2 b = ((const float2*)lnb)[li * 32 + lane];
    float2 hout;
    hout.x = (zx - mu) * rstd * g.x + b.x;
    hout.y = (zy - mu) * rstd * g.y + b.y;
    ((float2*)g_h)[n * 32 + lane] = hout;
}

// ---------------- head: out = relu(h@Wc1+bc1)@Wc2+bc2 -------------------------
__global__ void k_final(const float* __restrict__ Wc1, const float* __restrict__ bc1,
                        const float* __restrict__ Wc2, const float* __restrict__ bc2,
                        float* __restrict__ out) {
    __shared__ __align__(16) float hs[64 * 64];
    __shared__ __align__(16) float h1s[64 * 64];
    int t = threadIdx.x;
    int n0 = blockIdx.x * 64;
    float4* hs4 = (float4*)hs;
    for (int idx = t; idx < 1024; idx += 128) {
        int row = n0 + (idx >> 4);
        hs4[idx] = (row < N_NODES) ? ((const float4*)g_h)[row * 16 + (idx & 15)]
                                   : make_float4(0.f, 0.f, 0.f, 0.f);
    }
    int c = t & 63, rg = t >> 6;
    float wr[64];
    #pragma unroll
    for (int k = 0; k < 64; k++) wr[k] = Wc1[k * 64 + c];
    float b1 = bc1[c];
    __syncthreads();
    for (int r = rg * 32; r < rg * 32 + 32; r++) {
        const float4* hr = (const float4*)&hs[r * 64];
        float acc = b1;
        #pragma unroll
        for (int kk = 0; kk < 16; kk++) {
            float4 hv = hr[kk];
            acc = fmaf(wr[4 * kk + 0], hv.x, acc);
            acc = fmaf(wr[4 * kk + 1], hv.y, acc);
            acc = fmaf(wr[4 * kk + 2], hv.z, acc);
            acc = fmaf(wr[4 * kk + 3], hv.w, acc);
        }
        h1s[r * 64 + c] = fmaxf(acc, 0.f);
    }
    __syncthreads();
    if (t < 120) {
        int c2 = t % 12, rg2 = t / 12;
        float wr2[64];
        #pragma unroll
        for (int k = 0; k < 64; k++) wr2[k] = Wc2[k * NC + c2];
        float b2 = bc2[c2];
        int rmax = min(64, N_NODES - n0);
        for (int r = rg2; r < rmax; r += 10) {
            const float4* hr = (const float4*)&h1s[r * 64];
            float acc = b2;
            #pragma unroll
            for (int kk = 0; kk < 16; kk++) {
                float4 hv = hr[kk];
                acc = fmaf(wr2[4 * kk + 0], hv.x, acc);
                acc = fmaf(wr2[4 * kk + 1], hv.y, acc);
                acc = fmaf(wr2[4 * kk + 2], hv.z, acc);
                acc = fmaf(wr2[4 * kk + 3], hv.w, acc);
            }
            out[(n0 + r) * NC + c2] = acc;
        }
    }
}

// ---------------- launch -----------------------------------------------------
extern "C" void kernel_launch(void* const* d_in, const int* in_sizes, int n_in,
                              void* d_out, int out_size) {
    const float* x     = (const float*)d_in[0];
    const int*   ei    = (const int*)  d_in[1];
    const float* ea    = (const float*)d_in[2];
    const float* Win   = (const float*)d_in[3];
    const float* b_in  = (const float*)d_in[4];
    const float* Wq    = (const float*)d_in[5];
    const float* bq    = (const float*)d_in[6];
    const float* Wk    = (const float*)d_in[7];
    const float* bk    = (const float*)d_in[8];
    const float* Wv    = (const float*)d_in[9];
    const float* bv    = (const float*)d_in[10];
    const float* Wedge = (const float*)d_in[11];
    const float* Wskip = (const float*)d_in[12];
    const float* bskip = (const float*)d_in[13];
    const float* Wbeta = (const float*)d_in[14];
    const float* ln_g  = (const float*)d_in[15];
    const float* ln_b  = (const float*)d_in[16];
    const float* Wc1   = (const float*)d_in[17];
    const float* bc1   = (const float*)d_in[18];
    const float* Wc2   = (const float*)d_in[19];
    const float* bc2   = (const float*)d_in[20];
    float* out = (float*)d_out;

    int nrb = (N_NODES + 63) / 64;

    k_zero_cnt<<<(N_NODES + 255) / 256, 256>>>();
    k_hist<<<(N_EDGES + 255) / 256, 256>>>(ei);
    k_scan1<<<SCAN_BLK, 1024>>>();
    k_scan2<<<1, 64>>>();
    k_scan3<<<(N_NODES + 255) / 256, 256>>>();
    k_scatter<<<(N_EDGES + 255) / 256, 256>>>(ei, ea);

    k_ingemm<<<nrb, 64>>>(x, Win, b_in);

    for (int li = 0; li < NLAYERS; li++) {
        k_gemm4<<<nrb, 256>>>(li, Wq, bq, Wk, bk, Wv, bv, Wskip, bskip);
        k_node2<<<(N_NODES + 7) / 8, 256>>>(li, Wedge, Wbeta, ln_g, ln_b);
    }

    k_final<<<nrb, 128>>>(Wc1, bc1, Wc2, bc2, out);
}

// round 4
// speedup vs baseline: 1.2546x; 1.0430x over previous
#include <cuda_runtime.h>
#include <math.h>

#define N_NODES 50000
#define N_EDGES 800000
#define IN_DIM 50
#define HID 64
#define HEADS 4
#define NLAYERS 3
#define NC 12
#define INV_SQRT_C 0.25f
#define LN_EPS 1e-5f
#define SCAN_BLK ((N_NODES + 1023) / 1024)   // 49

typedef unsigned long long ull;

// packed f32x2 fma: d.lo = a.lo*b.lo + c.lo ; d.hi = a.hi*b.hi + c.hi
__device__ __forceinline__ ull ff2(ull a, ull b, ull c) {
    ull d;
    asm("fma.rn.f32x2 %0, %1, %2, %3;" : "=l"(d) : "l"(a), "l"(b), "l"(c));
    return d;
}
__device__ __forceinline__ ull packf2(float lo, float hi) {
    return ((ull)__float_as_uint(hi) << 32) | (ull)__float_as_uint(lo);
}
__device__ __forceinline__ float sum2(ull v) {
    return __uint_as_float((unsigned)(v & 0xffffffffu)) + __uint_as_float((unsigned)(v >> 32));
}

// ---------------- scratch (device globals; no allocation allowed) -------------
__device__ __align__(16) float g_h[N_NODES * HID];
__device__ __align__(16) float g_q[N_NODES * HID];
__device__ __align__(16) float g_k[N_NODES * HID];
__device__ __align__(16) float g_v[N_NODES * HID];
__device__ __align__(16) float g_skip[N_NODES * HID];
__device__ int   g_cnt[N_NODES];
__device__ int   g_rowptr[N_NODES + 1];
__device__ int   g_fill[N_NODES];
__device__ int   g_srcs[N_EDGES];
__device__ float g_eas[N_EDGES];
__device__ int   g_psum[64];

// ---------------- CSR build --------------------------------------------------
__global__ void k_zero_cnt() {
    int i = blockIdx.x * blockDim.x + threadIdx.x;
    if (i < N_NODES) g_cnt[i] = 0;
}

__global__ void k_hist(const int* __restrict__ ei) {
    int e = blockIdx.x * blockDim.x + threadIdx.x;
    if (e < N_EDGES) atomicAdd(&g_cnt[ei[N_EDGES + e]], 1);
}

__global__ void k_scan1() {
    __shared__ int wsum[32];
    int t = threadIdx.x, lane = t & 31, wid = t >> 5;
    int i = blockIdx.x * 1024 + t;
    int v = (i < N_NODES) ? g_cnt[i] : 0;
    int incl = v;
    #pragma unroll
    for (int o = 1; o < 32; o <<= 1) {
        int u = __shfl_up_sync(0xffffffffu, incl, o);
        if (lane >= o) incl += u;
    }
    if (lane == 31) wsum[wid] = incl;
    __syncthreads();
    if (wid == 0) {
        int ws = wsum[lane];
        int wincl = ws;
        #pragma unroll
        for (int o = 1; o < 32; o <<= 1) {
            int u = __shfl_up_sync(0xffffffffu, wincl, o);
            if (lane >= o) wincl += u;
        }
        wsum[lane] = wincl - ws;
        if (lane == 31) g_psum[blockIdx.x] = wincl;
    }
    __syncthreads();
    int excl = incl - v + wsum[wid];
    if (i < N_NODES) g_rowptr[i] = excl;
}

__global__ void k_scan2() {
    __shared__ int w0tot;
    int t = threadIdx.x, lane = t & 31;
    int v = (t < SCAN_BLK) ? g_psum[t] : 0;
    int incl = v;
    #pragma unroll
    for (int o = 1; o < 32; o <<= 1) {
        int u = __shfl_up_sync(0xffffffffu, incl, o);
        if (lane >= o) incl += u;
    }
    if (t == 31) w0tot = incl;
    __syncthreads();
    int excl = incl - v + ((t >= 32) ? w0tot : 0);
    if (t < SCAN_BLK) g_psum[t] = excl;
}

__global__ void k_scan3() {
    int i = blockIdx.x * blockDim.x + threadIdx.x;
    if (i < N_NODES) {
        int r = g_rowptr[i] + g_psum[i >> 10];
        g_rowptr[i] = r;
        g_fill[i] = r;
    }
    if (i == 0) g_rowptr[N_NODES] = N_EDGES;
}

__global__ void k_scatter(const int* __restrict__ ei, const float* __restrict__ ea) {
    int e = blockIdx.x * blockDim.x + threadIdx.x;
    if (e < N_EDGES) {
        int dst = ei[N_EDGES + e];
        int pos = atomicAdd(&g_fill[dst], 1);
        g_srcs[pos] = ei[e];
        g_eas[pos]  = ea[e];
    }
}

// ---------------- input GEMM: h = x @ Win + b_in (f32x2) ----------------------
__global__ void k_ingemm(const float* __restrict__ x,
                         const float* __restrict__ Win,
                         const float* __restrict__ b_in) {
    __shared__ __align__(16) float xs[64 * 52];
    int c = threadIdx.x;
    ull w2[26];
    #pragma unroll
    for (int k = 0; k < 25; k++)
        w2[k] = packf2(Win[(2 * k) * HID + c], Win[(2 * k + 1) * HID + c]);
    w2[25] = 0ull;
    int n0 = blockIdx.x * 64;
    for (int idx = c; idx < 64 * IN_DIM; idx += 64) {
        int r = idx / IN_DIM, k = idx % IN_DIM;
        int row = n0 + r;
        xs[r * 52 + k] = (row < N_NODES) ? x[row * IN_DIM + k] : 0.f;
    }
    xs[c * 52 + 50] = 0.f;
    xs[c * 52 + 51] = 0.f;
    __syncthreads();
    float bias = b_in[c];
    int rmax = min(64, N_NODES - n0);
    for (int r = 0; r < rmax; r++) {
        const ulonglong2* hr = (const ulonglong2*)&xs[r * 52];
        ull acc_a = packf2(bias, 0.f), acc_b = 0ull;
        #pragma unroll
        for (int kk = 0; kk < 13; kk++) {
            ulonglong2 hv = hr[kk];
            acc_a = ff2(w2[2 * kk + 0], hv.x, acc_a);
            acc_b = ff2(w2[2 * kk + 1], hv.y, acc_b);
        }
        g_h[(n0 + r) * HID + c] = sum2(acc_a) + sum2(acc_b);
    }
}

// ---------------- per-layer fused q/k/v/skip GEMM (f32x2) ---------------------
__global__ void k_gemm4(int li,
                        const float* __restrict__ Wq, const float* __restrict__ bq,
                        const float* __restrict__ Wk, const float* __restrict__ bk,
                        const float* __restrict__ Wv, const float* __restrict__ bv,
                        const float* __restrict__ Wsk, const float* __restrict__ bsk) {
    __shared__ __align__(16) float hs[64 * 64];
    int t = threadIdx.x;
    int mat = t >> 6, c = t & 63;
    const float* W; const float* b; float* out;
    if (mat == 0)      { W = Wq  + li * 4096; b = bq  + li * 64; out = g_q; }
    else if (mat == 1) { W = Wk  + li * 4096; b = bk  + li * 64; out = g_k; }
    else if (mat == 2) { W = Wv  + li * 4096; b = bv  + li * 64; out = g_v; }
    else               { W = Wsk + li * 4096; b = bsk + li * 64; out = g_skip; }
    float scal = (mat == 0) ? INV_SQRT_C : 1.f;   // fold q-scale into weights
    ull w2[32];
    #pragma unroll
    for (int k = 0; k < 32; k++)
        w2[k] = packf2(W[(2 * k) * 64 + c] * scal, W[(2 * k + 1) * 64 + c] * scal);
    float bias = b[c] * scal;
    int n0 = blockIdx.x * 64;
    float4* hs4 = (float4*)hs;
    for (int idx = t; idx < 1024; idx += 256) {
        int row = n0 + (idx >> 4);
        hs4[idx] = (row < N_NODES) ? ((const float4*)g_h)[row * 16 + (idx & 15)]
                                   : make_float4(0.f, 0.f, 0.f, 0.f);
    }
    __syncthreads();
    int rmax = min(64, N_NODES - n0);
    for (int r = 0; r < rmax; r++) {
        const ulonglong2* hr = (const ulonglong2*)&hs[r * 64];
        ull acc_a = packf2(bias, 0.f), acc_b = 0ull;
        #pragma unroll
        for (int kk = 0; kk < 16; kk++) {
            ulonglong2 hv = hr[kk];
            acc_a = ff2(w2[2 * kk + 0], hv.x, acc_a);
            acc_b = ff2(w2[2 * kk + 1], hv.y, acc_b);
        }
        out[(n0 + r) * 64 + c] = sum2(acc_a) + sum2(acc_b);
    }
}

// ---------------- fused node kernel: warp per node ---------------------------
__global__ void k_node2(int li,
                        const float* __restrict__ Wedge,
                        const float* __restrict__ Wbeta,
                        const float* __restrict__ lng,
                        const float* __restrict__ lnb) {
    int n = blockIdx.x * (blockDim.x >> 5) + (threadIdx.x >> 5);
    if (n >= N_NODES) return;
    int lane = threadIdx.x & 31;

    float2 q  = ((const float2*)g_q)[n * 32 + lane];          // pre-scaled
    float2 we = ((const float2*)Wedge)[li * 32 + lane];

    float pw = q.x * we.x + q.y * we.y;
    pw += __shfl_xor_sync(0xffffffffu, pw, 4, 8);
    pw += __shfl_xor_sync(0xffffffffu, pw, 2, 8);
    pw += __shfl_xor_sync(0xffffffffu, pw, 1, 8);
    float qwe = pw;

    float d = 0.f, spw = 0.f;
    float ax = 0.f, ay = 0.f;
    int j0 = g_rowptr[n], j1 = g_rowptr[n + 1];
    for (int j = j0; j < j1; j++) {
        int   s = __ldg(&g_srcs[j]);
        float w = __ldg(&g_eas[j]);
        float2 kf = ((const float2*)g_k)[s * 32 + lane];
        float p = q.x * kf.x + q.y * kf.y;
        p += __shfl_xor_sync(0xffffffffu, p, 4, 8);
        p += __shfl_xor_sync(0xffffffffu, p, 2, 8);
        p += __shfl_xor_sync(0xffffffffu, p, 1, 8);
        float a  = fmaf(w, qwe, p);
        float ex = __expf(a);                 // shift-invariant; logits O(1)
        float2 vf = ((const float2*)g_v)[s * 32 + lane];
        d   += ex;
        ax   = fmaf(ex, vf.x, ax);
        ay   = fmaf(ex, vf.y, ay);
        spw  = fmaf(ex, w, spw);
    }
    float inv = 1.f / (d + 1e-16f);
    float ox = (ax + we.x * spw) * inv;
    float oy = (ay + we.y * spw) * inv;

    float2 xr = ((const float2*)g_skip)[n * 32 + lane];
    const float2* Wb = (const float2*)(Wbeta + li * 192);
    float2 w1 = Wb[lane], w2 = Wb[32 + lane], w3 = Wb[64 + lane];
    float contrib = ox * w1.x + oy * w1.y + xr.x * w2.x + xr.y * w2.y
                  + (ox - xr.x) * w3.x + (oy - xr.y) * w3.y;
    #pragma unroll
    for (int o = 16; o >= 1; o >>= 1)
        contrib += __shfl_xor_sync(0xffffffffu, contrib, o);
    float beta = 1.f / (1.f + __expf(-contrib));

    float2 hres = ((const float2*)g_h)[n * 32 + lane];
    float zx = fmaf(beta, xr.x - ox, ox) + hres.x;
    float zy = fmaf(beta, xr.y - oy, oy) + hres.y;

    float s1 = zx + zy;
    float s2 = zx * zx + zy * zy;
    #pragma unroll
    for (int o = 16; o >= 1; o >>= 1) {
        s1 += __shfl_xor_sync(0xffffffffu, s1, o);
        s2 += __shfl_xor_sync(0xffffffffu, s2, o);
    }
    float mu  = s1 * (1.f / 64.f);
    float var = s2 * (1.f / 64.f) - mu * mu;
    float rstd = rsqrtf(var + LN_EPS);
    float2 g = ((const float2*)lng)[li * 32 + lane];
    float2 b = ((const float2*)lnb)[li * 32 + lane];
    float2 hout;
    hout.x = (zx - mu) * rstd * g.x + b.x;
    hout.y = (zy - mu) * rstd * g.y + b.y;
    ((float2*)g_h)[n * 32 + lane] = hout;
}

// ---------------- head: out = relu(h@Wc1+bc1)@Wc2+bc2 (f32x2, 256 thr) --------
__global__ void k_final(const float* __restrict__ Wc1, const float* __restrict__ bc1,
                        const float* __restrict__ Wc2, const float* __restrict__ bc2,
                        float* __restrict__ out) {
    __shared__ __align__(16) float hs[64 * 64];
    __shared__ __align__(16) float h1s[64 * 64];
    int t = threadIdx.x;
    int n0 = blockIdx.x * 64;
    float4* hs4 = (float4*)hs;
    for (int idx = t; idx < 1024; idx += 256) {
        int row = n0 + (idx >> 4);
        hs4[idx] = (row < N_NODES) ? ((const float4*)g_h)[row * 16 + (idx & 15)]
                                   : make_float4(0.f, 0.f, 0.f, 0.f);
    }
    int c = t & 63, rg = t >> 6;       // 4 row-groups of 16
    ull w2[32];
    #pragma unroll
    for (int k = 0; k < 32; k++)
        w2[k] = packf2(Wc1[(2 * k) * 64 + c], Wc1[(2 * k + 1) * 64 + c]);
    float b1 = bc1[c];
    __syncthreads();
    for (int r = rg * 16; r < rg * 16 + 16; r++) {
        const ulonglong2* hr = (const ulonglong2*)&hs[r * 64];
        ull acc_a = packf2(b1, 0.f), acc_b = 0ull;
        #pragma unroll
        for (int kk = 0; kk < 16; kk++) {
            ulonglong2 hv = hr[kk];
            acc_a = ff2(w2[2 * kk + 0], hv.x, acc_a);
            acc_b = ff2(w2[2 * kk + 1], hv.y, acc_b);
        }
        h1s[r * 64 + c] = fmaxf(sum2(acc_a) + sum2(acc_b), 0.f);
    }
    __syncthreads();
    if (t < 240) {
        int c2 = t % 12, rg2 = t / 12;   // 20 row-groups
        ull wr2[32];
        #pragma unroll
        for (int k = 0; k < 32; k++)
            wr2[k] = packf2(Wc2[(2 * k) * NC + c2], Wc2[(2 * k + 1) * NC + c2]);
        float b2 = bc2[c2];
        int rmax = min(64, N_NODES - n0);
        for (int r = rg2; r < rmax; r += 20) {
            const ulonglong2* hr = (const ulonglong2*)&h1s[r * 64];
            ull acc_a = packf2(b2, 0.f), acc_b = 0ull;
            #pragma unroll
            for (int kk = 0; kk < 16; kk++) {
                ulonglong2 hv = hr[kk];
                acc_a = ff2(wr2[2 * kk + 0], hv.x, acc_a);
                acc_b = ff2(wr2[2 * kk + 1], hv.y, acc_b);
            }
            out[(n0 + r) * NC + c2] = sum2(acc_a) + sum2(acc_b);
        }
    }
}

// ---------------- launch -----------------------------------------------------
extern "C" void kernel_launch(void* const* d_in, const int* in_sizes, int n_in,
                              void* d_out, int out_size) {
    const float* x     = (const float*)d_in[0];
    const int*   ei    = (const int*)  d_in[1];
    const float* ea    = (const float*)d_in[2];
    const float* Win   = (const float*)d_in[3];
    const float* b_in  = (const float*)d_in[4];
    const float* Wq    = (const float*)d_in[5];
    const float* bq    = (const float*)d_in[6];
    const float* Wk    = (const float*)d_in[7];
    const float* bk    = (const float*)d_in[8];
    const float* Wv    = (const float*)d_in[9];
    const float* bv    = (const float*)d_in[10];
    const float* Wedge = (const float*)d_in[11];
    const float* Wskip = (const float*)d_in[12];
    const float* bskip = (const float*)d_in[13];
    const float* Wbeta = (const float*)d_in[14];
    const float* ln_g  = (const float*)d_in[15];
    const float* ln_b  = (const float*)d_in[16];
    const float* Wc1   = (const float*)d_in[17];
    const float* bc1   = (const float*)d_in[18];
    const float* Wc2   = (const float*)d_in[19];
    const float* bc2   = (const float*)d_in[20];
    float* out = (float*)d_out;

    int nrb = (N_NODES + 63) / 64;

    k_zero_cnt<<<(N_NODES + 255) / 256, 256>>>();
    k_hist<<<(N_EDGES + 255) / 256, 256>>>(ei);
    k_scan1<<<SCAN_BLK, 1024>>>();
    k_scan2<<<1, 64>>>();
    k_scan3<<<(N_NODES + 255) / 256, 256>>>();
    k_scatter<<<(N_EDGES + 255) / 256, 256>>>(ei, ea);

    k_ingemm<<<nrb, 64>>>(x, Win, b_in);

    for (int li = 0; li < NLAYERS; li++) {
        k_gemm4<<<nrb, 256>>>(li, Wq, bq, Wk, bk, Wv, bv, Wskip, bskip);
        k_node2<<<(N_NODES + 7) / 8, 256>>>(li, Wedge, Wbeta, ln_g, ln_b);
    }

    k_final<<<nrb, 256>>>(Wc1, bc1, Wc2, bc2, out);
}